// round 8
// baseline (speedup 1.0000x reference)
#include <cuda_runtime.h>
#include <cuda_bf16.h>

// DistMult edge scoring:
//   out[r, e] = sigmoid( sum_d h[src[r,e], d] * W[r, d] * h[dst[r,e], d] )
// h [100000,128] f32, W [6,128] f32, src/dst [6,200000] int32, out [6,200000] f32.
//
// R8: R7's LDS-for-W regression showed W reads compete with row LDGs for
// the L1tex pipe. Move W to __constant__ memory (LDC -> constant port, off
// L1tex, zero permanent regs), keep index preload in smem (cheap), keep the
// 8x LDG.128 row burst and __launch_bounds__(256,5) occupancy (40 warps/SM).
// cudaMemcpyToSymbolAsync (D2D, async) is graph-capturable and alloc-free.

#define N_HID 128
#define E_PER_REL 200000
#define N_REL 6
#define BLOCK 256
#define EDGES_PER_BLOCK 32      // 256 threads / 8 lanes per edge
#define GRID_X 1250             // 1250 * 32 * 5 == 200000 exactly
#define ITERS 5
#define STRIDE (GRID_X * EDGES_PER_BLOCK)   // 40000

__constant__ float4 cW[N_REL][N_HID / 4];   // 3 KB

__global__ __launch_bounds__(BLOCK, 5)
void distmult_kernel(const float4* __restrict__ h4,
                     const int* __restrict__ src_idx,
                     const int* __restrict__ dst_idx,
                     float* __restrict__ out) {
    __shared__ int Sidx[ITERS * EDGES_PER_BLOCK];  // 160 ints
    __shared__ int Didx[ITERS * EDGES_PER_BLOCK];  // 160 ints

    const int rel   = blockIdx.y;
    const int tid   = threadIdx.x;
    const int sub   = tid & 7;     // lane within 8-lane edge group
    const int group = tid >> 3;    // edge slot within block: 0..31

    const int* __restrict__ srcR = src_idx + rel * E_PER_REL;
    const int* __restrict__ dstR = dst_idx + rel * E_PER_REL;
    float* __restrict__ outR = out + rel * E_PER_REL;

    // Prologue: preload all phase indices, coalesced.
    if (tid < ITERS * EDGES_PER_BLOCK) {
        const int i = tid >> 5;          // phase
        const int g = tid & 31;          // group slot
        const int e = blockIdx.x * EDGES_PER_BLOCK + i * STRIDE + g;
        Sidx[tid] = __ldg(srcR + e);
        Didx[tid] = __ldg(dstR + e);
    }
    __syncthreads();

    const int e0 = blockIdx.x * EDGES_PER_BLOCK + group;

    #pragma unroll
    for (int i = 0; i < ITERS; i++) {
        const int s = Sidx[i * EDGES_PER_BLOCK + group];   // LDS broadcast
        const int d = Didx[i * EDGES_PER_BLOCK + group];

        const float4* __restrict__ hs = h4 + (long long)s * (N_HID / 4);
        const float4* __restrict__ hd = h4 + (long long)d * (N_HID / 4);

        // 8 independent 16B row loads in flight per thread (the only L1tex
        // data traffic in the phase).
        float4 a0 = __ldg(hs + sub);
        float4 a1 = __ldg(hs + sub + 8);
        float4 a2 = __ldg(hs + sub + 16);
        float4 a3 = __ldg(hs + sub + 24);
        float4 b0 = __ldg(hd + sub);
        float4 b1 = __ldg(hd + sub + 8);
        float4 b2 = __ldg(hd + sub + 16);
        float4 b3 = __ldg(hd + sub + 24);

        // W chunks from constant memory: warp-uniform LDC, constant port,
        // no L1tex traffic, no permanent registers.
        const float4 w0 = cW[rel][sub];
        const float4 w1 = cW[rel][sub + 8];
        const float4 w2 = cW[rel][sub + 16];
        const float4 w3 = cW[rel][sub + 24];

        float acc;
        acc = a0.x * w0.x * b0.x;
        acc = fmaf(a0.y * w0.y, b0.y, acc);
        acc = fmaf(a0.z * w0.z, b0.z, acc);
        acc = fmaf(a0.w * w0.w, b0.w, acc);
        acc = fmaf(a1.x * w1.x, b1.x, acc);
        acc = fmaf(a1.y * w1.y, b1.y, acc);
        acc = fmaf(a1.z * w1.z, b1.z, acc);
        acc = fmaf(a1.w * w1.w, b1.w, acc);
        acc = fmaf(a2.x * w2.x, b2.x, acc);
        acc = fmaf(a2.y * w2.y, b2.y, acc);
        acc = fmaf(a2.z * w2.z, b2.z, acc);
        acc = fmaf(a2.w * w2.w, b2.w, acc);
        acc = fmaf(a3.x * w3.x, b3.x, acc);
        acc = fmaf(a3.y * w3.y, b3.y, acc);
        acc = fmaf(a3.z * w3.z, b3.z, acc);
        acc = fmaf(a3.w * w3.w, b3.w, acc);

        // Reduce across the 8-lane group.
        acc += __shfl_xor_sync(0xFFFFFFFFu, acc, 4);
        acc += __shfl_xor_sync(0xFFFFFFFFu, acc, 2);
        acc += __shfl_xor_sync(0xFFFFFFFFu, acc, 1);

        if (sub == 0)
            outR[e0 + i * STRIDE] = 1.0f / (1.0f + __expf(-acc));
    }
}

extern "C" void kernel_launch(void* const* d_in, const int* in_sizes, int n_in,
                              void* d_out, int out_size) {
    const float4* h4 = (const float4*)d_in[0];
    const float*  W  = (const float*)d_in[1];
    const int*   src = (const int*)d_in[2];
    const int*   dst = (const int*)d_in[3];
    float* out = (float*)d_out;

    // Stage W into constant memory (D2D async copy: graph-capturable,
    // no allocation). Deterministic: same W every call.
    cudaMemcpyToSymbolAsync(cW, W, N_REL * N_HID * sizeof(float), 0,
                            cudaMemcpyDeviceToDevice);

    dim3 grid(GRID_X, N_REL);
    distmult_kernel<<<grid, BLOCK>>>(h4, src, dst, out);
}

// round 9
// speedup vs baseline: 1.4145x; 1.4145x over previous
#include <cuda_runtime.h>
#include <cuda_bf16.h>

// DistMult edge scoring:
//   out[r, e] = sigmoid( sum_d h[src[r,e], d] * W[r, d] * h[dst[r,e], d] )
// h [100000,128] f32, W [6,128] f32, src/dst [6,200000] int32, out [6,200000] f32.
//
// R9: occupancy via SMALLER per-thread footprint, W kept in registers
// (R7/R8 showed off-RF W regresses). 16 lanes/edge, 2 edges/warp:
// W = 8 regs, row burst = 16 regs, indices preloaded in smem.
// Target regs <= 42 -> 6 CTAs = 48 warps/SM (vs 32 in R6).
// LDG.128 count per byte unchanged; MLP = 8 loads/warp front-batched.

#define N_HID 128
#define E_PER_REL 200000
#define N_REL 6
#define BLOCK 256
#define EDGES_PER_BLOCK 16      // 256 threads / 16 lanes per edge
#define GRID_X 2500             // 2500 * 16 * 5 == 200000 exactly
#define ITERS 5
#define STRIDE (GRID_X * EDGES_PER_BLOCK)   // 40000

__global__ __launch_bounds__(BLOCK, 6)
void distmult_kernel(const float4* __restrict__ h4,
                     const float4* __restrict__ W4,
                     const int* __restrict__ src_idx,
                     const int* __restrict__ dst_idx,
                     float* __restrict__ out) {
    __shared__ int Sidx[ITERS * EDGES_PER_BLOCK];  // 80 ints
    __shared__ int Didx[ITERS * EDGES_PER_BLOCK];  // 80 ints

    const int rel   = blockIdx.y;
    const int tid   = threadIdx.x;
    const int sub   = tid & 15;    // lane within 16-lane edge group
    const int group = tid >> 4;    // edge slot within block: 0..15

    const int* __restrict__ srcR = src_idx + rel * E_PER_REL;
    const int* __restrict__ dstR = dst_idx + rel * E_PER_REL;
    float* __restrict__ outR = out + rel * E_PER_REL;

    // This relation's W row in registers: lane sub owns chunks {sub, sub+16}.
    const float4* __restrict__ wr = W4 + rel * (N_HID / 4);
    const float4 w0 = __ldg(wr + sub);
    const float4 w1 = __ldg(wr + sub + 16);

    // Prologue: preload all phase indices, coalesced.
    if (tid < ITERS * EDGES_PER_BLOCK) {
        const int i = tid >> 4;          // phase
        const int g = tid & 15;          // group slot
        const int e = blockIdx.x * EDGES_PER_BLOCK + i * STRIDE + g;
        Sidx[tid] = __ldg(srcR + e);
        Didx[tid] = __ldg(dstR + e);
    }
    __syncthreads();

    const int e0 = blockIdx.x * EDGES_PER_BLOCK + group;

    #pragma unroll
    for (int i = 0; i < ITERS; i++) {
        const int s = Sidx[i * EDGES_PER_BLOCK + group];   // LDS broadcast
        const int d = Didx[i * EDGES_PER_BLOCK + group];

        const float4* __restrict__ hs = h4 + s * (N_HID / 4);
        const float4* __restrict__ hd = h4 + d * (N_HID / 4);

        // 4 independent 16B loads per thread, 8 per warp-edge-pair,
        // all front-batched.
        float4 a0 = __ldg(hs + sub);
        float4 a1 = __ldg(hs + sub + 16);
        float4 b0 = __ldg(hd + sub);
        float4 b1 = __ldg(hd + sub + 16);

        float acc;
        acc = a0.x * w0.x * b0.x;
        acc = fmaf(a0.y * w0.y, b0.y, acc);
        acc = fmaf(a0.z * w0.z, b0.z, acc);
        acc = fmaf(a0.w * w0.w, b0.w, acc);
        acc = fmaf(a1.x * w1.x, b1.x, acc);
        acc = fmaf(a1.y * w1.y, b1.y, acc);
        acc = fmaf(a1.z * w1.z, b1.z, acc);
        acc = fmaf(a1.w * w1.w, b1.w, acc);

        // Reduce across the 16-lane group (xor offsets < 16 stay in-group).
        acc += __shfl_xor_sync(0xFFFFFFFFu, acc, 8);
        acc += __shfl_xor_sync(0xFFFFFFFFu, acc, 4);
        acc += __shfl_xor_sync(0xFFFFFFFFu, acc, 2);
        acc += __shfl_xor_sync(0xFFFFFFFFu, acc, 1);

        if (sub == 0)
            outR[e0 + i * STRIDE] = 1.0f / (1.0f + __expf(-acc));
    }
}

extern "C" void kernel_launch(void* const* d_in, const int* in_sizes, int n_in,
                              void* d_out, int out_size) {
    const float4* h4 = (const float4*)d_in[0];
    const float4* W4 = (const float4*)d_in[1];
    const int*   src = (const int*)d_in[2];
    const int*   dst = (const int*)d_in[3];
    float* out = (float*)d_out;

    dim3 grid(GRID_X, N_REL);
    distmult_kernel<<<grid, BLOCK>>>(h4, W4, src, dst, out);
}

// round 11
// speedup vs baseline: 1.5050x; 1.0640x over previous
#include <cuda_runtime.h>
#include <cuda_bf16.h>
#include <cstdint>

// DistMult edge scoring:
//   out[r, e] = sigmoid( sum_d h[src[r,e], d] * W[r, d] * h[dst[r,e], d] )
// h [100000,128] f32, W [6,128] f32, src/dst [6,200000] int32, out [6,200000] f32.
//
// R11: R10 with the row-stride bug fixed. ulonglong2 = 4 floats, so a
// 128-float row = 32 ulonglong2 (R10 wrongly used 16 -> gathered wrong rows).
// Packed f32x2 math (mul/fma.rn.f32x2, PTX-only) halves fp issue per
// element; 16 lanes/edge keeps regs ~40 -> 6 CTAs = 48 warps/SM; indices
// preloaded to smem as int2 (one LDS.64 broadcast per phase); 4 front-
// batched LDG.128 per thread per phase.

#define N_HID 128
#define E_PER_REL 200000
#define N_REL 6
#define BLOCK 256
#define EDGES_PER_BLOCK 16      // 256 threads / 16 lanes per edge
#define GRID_X 2500             // 2500 * 16 * 5 == 200000 exactly
#define ITERS 5
#define STRIDE (GRID_X * EDGES_PER_BLOCK)   // 40000
#define ROW_U2 (N_HID / 4)      // 32 ulonglong2 per 128-float row

__device__ __forceinline__ unsigned long long f32x2_mul(unsigned long long a,
                                                        unsigned long long b) {
    unsigned long long r;
    asm("mul.rn.f32x2 %0, %1, %2;" : "=l"(r) : "l"(a), "l"(b));
    return r;
}
__device__ __forceinline__ unsigned long long f32x2_fma(unsigned long long a,
                                                        unsigned long long b,
                                                        unsigned long long c) {
    unsigned long long r;
    asm("fma.rn.f32x2 %0, %1, %2, %3;" : "=l"(r) : "l"(a), "l"(b), "l"(c));
    return r;
}

__global__ __launch_bounds__(BLOCK, 6)
void distmult_kernel(const ulonglong2* __restrict__ h8,   // row = 32 x ulonglong2
                     const ulonglong2* __restrict__ W8,
                     const int* __restrict__ src_idx,
                     const int* __restrict__ dst_idx,
                     float* __restrict__ out) {
    __shared__ int2 SD[ITERS * EDGES_PER_BLOCK];   // packed (s,d), 640 B

    const int rel   = blockIdx.y;
    const int tid   = threadIdx.x;
    const int sub   = tid & 15;    // lane within 16-lane edge group
    const int group = tid >> 4;    // edge slot within block: 0..15

    const int* __restrict__ srcR = src_idx + rel * E_PER_REL;
    const int* __restrict__ dstR = dst_idx + rel * E_PER_REL;
    float* __restrict__ outR = out + rel * E_PER_REL;

    // W row in registers: lane sub owns ulonglong2 chunks {sub, sub+16} of 32.
    const ulonglong2 w0 = W8[rel * ROW_U2 + sub];
    const ulonglong2 w1 = W8[rel * ROW_U2 + sub + 16];

    // Prologue: preload all phase (s,d) pairs, coalesced.
    if (tid < ITERS * EDGES_PER_BLOCK) {
        const int i = tid >> 4;          // phase
        const int g = tid & 15;          // group slot
        const int e = blockIdx.x * EDGES_PER_BLOCK + i * STRIDE + g;
        SD[tid] = make_int2(__ldg(srcR + e), __ldg(dstR + e));
    }
    __syncthreads();

    const int e0 = blockIdx.x * EDGES_PER_BLOCK + group;

    #pragma unroll
    for (int i = 0; i < ITERS; i++) {
        const int2 sd = SD[i * EDGES_PER_BLOCK + group];   // one LDS.64, broadcast

        const ulonglong2* __restrict__ hs = h8 + (long long)sd.x * ROW_U2;
        const ulonglong2* __restrict__ hd = h8 + (long long)sd.y * ROW_U2;

        // 4 independent LDG.128 per thread, front-batched.
        ulonglong2 a0 = hs[sub];
        ulonglong2 a1 = hs[sub + 16];
        ulonglong2 b0 = hd[sub];
        ulonglong2 b1 = hd[sub + 16];

        // Packed math: 4 mul.f32x2 + 3 fma.f32x2 + 1 mul covers 8 dims.
        unsigned long long acc2;
        acc2 = f32x2_mul(f32x2_mul(a0.x, b0.x), w0.x);
        acc2 = f32x2_fma(f32x2_mul(a0.y, b0.y), w0.y, acc2);
        acc2 = f32x2_fma(f32x2_mul(a1.x, b1.x), w1.x, acc2);
        acc2 = f32x2_fma(f32x2_mul(a1.y, b1.y), w1.y, acc2);

        // Fold the two packed halves.
        float lo = __uint_as_float((unsigned)(acc2 & 0xFFFFFFFFull));
        float hi = __uint_as_float((unsigned)(acc2 >> 32));
        float acc = lo + hi;

        // Reduce across the 16-lane group.
        acc += __shfl_xor_sync(0xFFFFFFFFu, acc, 8);
        acc += __shfl_xor_sync(0xFFFFFFFFu, acc, 4);
        acc += __shfl_xor_sync(0xFFFFFFFFu, acc, 2);
        acc += __shfl_xor_sync(0xFFFFFFFFu, acc, 1);

        if (sub == 0)
            outR[e0 + i * STRIDE] = 1.0f / (1.0f + __expf(-acc));
    }
}

extern "C" void kernel_launch(void* const* d_in, const int* in_sizes, int n_in,
                              void* d_out, int out_size) {
    const ulonglong2* h8 = (const ulonglong2*)d_in[0];
    const ulonglong2* W8 = (const ulonglong2*)d_in[1];
    const int* src = (const int*)d_in[2];
    const int* dst = (const int*)d_in[3];
    float* out = (float*)d_out;

    dim3 grid(GRID_X, N_REL);
    distmult_kernel<<<grid, BLOCK>>>(h8, W8, src, dst, out);
}